// round 4
// baseline (speedup 1.0000x reference)
#include <cuda_runtime.h>
#include <math_constants.h>

// GaussianVector_box — two-phase:
//   1) param kernel: per-box window/sigma params (divides, floors, bounds) once,
//      into 1 MB __device__ scratch (L2-resident for phase 2).
//   2) splat kernel: barrier-free pure store streamer. 268 MB of f32 writes.
//
// Output layout: [vector_x (B*N*1024)] ++ [vector_y (B*N*1024)], f32.

#define OUT_W 1024
#define OUT_H 1024
#define BN_MAX 32768

// {x, ul, br, -1/(2*sigma^2)} per axis per box. Inactive boxes encode an
// empty window (ul=+inf, br=-inf) so every lane writes zero.
__device__ float4 g_px[BN_MAX];
__device__ float4 g_py[BN_MAX];

__global__ __launch_bounds__(256)
void gv_param_kernel(const float* __restrict__ centers,
                     const float* __restrict__ whs, int BN)
{
    const int i = blockIdx.x * blockDim.x + threadIdx.x;
    if (i >= BN) return;

    const float2 c  = __ldg(((const float2*)centers) + i);
    const float2 wh = __ldg(((const float2*)whs) + i);

    // ks = floor(W/2)*2 - 1 ; r = (ks-1)/2 = floor(W/2) - 1 (exact) ; s = floor(r/3)
    const float rw = floorf(wh.x * 0.5f) - 1.0f;
    const float rh = floorf(wh.y * 0.5f) - 1.0f;
    const float sw = floorf(rw / 3.0f);
    const float sh = floorf(rh / 3.0f);

    const bool zero_box = (c.x + c.y + wh.x + wh.y) == 0.0f;

    // SCALE = 1 ; astype(int32) truncates toward zero
    const float x = truncf(c.x);
    const float y = truncf(c.y);

    float ul0 = x - rw, ul1 = y - rh;
    float br0 = x + rw + 1.0f, br1 = y + rh + 1.0f;

    const bool in_ul = (ul0 >= 0.0f) & (ul0 <= (float)OUT_W) &
                       (ul1 >= 0.0f) & (ul1 <= (float)OUT_H);
    const bool in_br = (br0 >= 0.0f) & (br0 <= (float)OUT_W) &
                       (br1 >= 0.0f) & (br1 <= (float)OUT_H);

    const bool active = (!zero_box) & (sw != 0.0f) & (sh != 0.0f) & (in_ul | in_br);

    if (!active) {
        ul0 = CUDART_INF_F;  br0 = -CUDART_INF_F;
        ul1 = CUDART_INF_F;  br1 = -CUDART_INF_F;
    }

    const float kx = -0.5f / (sw * sw);
    const float ky = -0.5f / (sh * sh);

    g_px[i] = make_float4(x, ul0, br0, kx);
    g_py[i] = make_float4(y, ul1, br1, ky);
}

__global__ __launch_bounds__(256, 8)
void gv_splat_kernel(float* __restrict__ out_x, float* __restrict__ out_y)
{
    const int bn = blockIdx.x;
    const int t  = threadIdx.x;

    // Uniform (warp-broadcast) param loads — L1/L2 hits.
    const float4 Px = __ldg(&g_px[bn]);
    const float4 Py = __ldg(&g_py[bn]);

    const float c0 = (float)(t << 2);

    float4 vx = make_float4(0.f, 0.f, 0.f, 0.f);
    if ((c0 + 3.0f) >= Px.y && c0 < Px.z) {
        #pragma unroll
        for (int j = 0; j < 4; ++j) {
            float p = c0 + (float)j;
            if (p >= Px.y && p < Px.z) {
                float d = p - Px.x;
                float v = __expf(d * d * Px.w);
                if (j == 0) vx.x = v; else if (j == 1) vx.y = v;
                else if (j == 2) vx.z = v; else vx.w = v;
            }
        }
    }

    float4 vy = make_float4(0.f, 0.f, 0.f, 0.f);
    if ((c0 + 3.0f) >= Py.y && c0 < Py.z) {
        #pragma unroll
        for (int j = 0; j < 4; ++j) {
            float p = c0 + (float)j;
            if (p >= Py.y && p < Py.z) {
                float d = p - Py.x;
                float v = __expf(d * d * Py.w);
                if (j == 0) vy.x = v; else if (j == 1) vy.y = v;
                else if (j == 2) vy.z = v; else vy.w = v;
            }
        }
    }

    // Streaming (evict-first) 128-bit stores.
    __stcs(((float4*)(out_x + (size_t)bn * OUT_W)) + t, vx);
    __stcs(((float4*)(out_y + (size_t)bn * OUT_H)) + t, vy);
}

extern "C" void kernel_launch(void* const* d_in, const int* in_sizes, int n_in,
                              void* d_out, int out_size)
{
    const float* centers = (const float*)d_in[0];  // [B,N,2]
    const float* whs     = (const float*)d_in[1];  // [B,N,2]
    float* out = (float*)d_out;

    const int BN = in_sizes[0] / 2;                // 128*256 = 32768
    float* out_x = out;
    float* out_y = out + (size_t)BN * OUT_W;

    gv_param_kernel<<<(BN + 255) / 256, 256>>>(centers, whs, BN);
    gv_splat_kernel<<<BN, 256>>>(out_x, out_y);
}

// round 5
// speedup vs baseline: 1.0332x; 1.0332x over previous
#include <cuda_runtime.h>
#include <math_constants.h>

// GaussianVector_box — two-phase with PDL overlap + zero-store-first splat.
//   1) param kernel (32K threads, ~2us): per-box window/sigma params into
//      __device__ scratch (L2-resident).
//   2) splat kernel (PDL): every thread streams its 2 float4 ZEROS immediately
//      (no dependency), then grid-syncs on the param kernel, and only the ~7%
//      of float4s inside a gaussian window issue a second overwrite store.
//      Overwrites land while lines are still in L2 -> no extra DRAM traffic.
//
// Output: [vector_x (B*N*1024)] ++ [vector_y (B*N*1024)], f32, 268 MB writes.

#define OUT_W 1024
#define OUT_H 1024
#define BN_MAX 32768

// {x, ul, br, -1/(2*sigma^2)} per axis per box. Inactive boxes encode an
// empty window (ul=+inf, br=-inf) so no overwrite store happens.
__device__ float4 g_px[BN_MAX];
__device__ float4 g_py[BN_MAX];

__global__ __launch_bounds__(256)
void gv_param_kernel(const float* __restrict__ centers,
                     const float* __restrict__ whs, int BN)
{
    const int i = blockIdx.x * blockDim.x + threadIdx.x;
    if (i >= BN) return;

    const float2 c  = __ldg(((const float2*)centers) + i);
    const float2 wh = __ldg(((const float2*)whs) + i);

    // ks = floor(W/2)*2 - 1 ; r = (ks-1)/2 = floor(W/2) - 1 (exact) ; s = floor(r/3)
    const float rw = floorf(wh.x * 0.5f) - 1.0f;
    const float rh = floorf(wh.y * 0.5f) - 1.0f;
    const float sw = floorf(rw / 3.0f);
    const float sh = floorf(rh / 3.0f);

    const bool zero_box = (c.x + c.y + wh.x + wh.y) == 0.0f;

    // SCALE = 1 ; astype(int32) truncates toward zero
    const float x = truncf(c.x);
    const float y = truncf(c.y);

    float ul0 = x - rw, ul1 = y - rh;
    float br0 = x + rw + 1.0f, br1 = y + rh + 1.0f;

    const bool in_ul = (ul0 >= 0.0f) & (ul0 <= (float)OUT_W) &
                       (ul1 >= 0.0f) & (ul1 <= (float)OUT_H);
    const bool in_br = (br0 >= 0.0f) & (br0 <= (float)OUT_W) &
                       (br1 >= 0.0f) & (br1 <= (float)OUT_H);

    const bool active = (!zero_box) & (sw != 0.0f) & (sh != 0.0f) & (in_ul | in_br);

    if (!active) {
        ul0 = CUDART_INF_F;  br0 = -CUDART_INF_F;
        ul1 = CUDART_INF_F;  br1 = -CUDART_INF_F;
    }

    const float kx = -0.5f / (sw * sw);
    const float ky = -0.5f / (sh * sh);

    g_px[i] = make_float4(x, ul0, br0, kx);
    g_py[i] = make_float4(y, ul1, br1, ky);
}

__global__ __launch_bounds__(256, 8)
void gv_splat_kernel(float* __restrict__ out_x, float* __restrict__ out_y)
{
    const int bn = blockIdx.x;
    const int t  = threadIdx.x;

    float4* px_addr = ((float4*)(out_x + (size_t)bn * OUT_W)) + t;
    float4* py_addr = ((float4*)(out_y + (size_t)bn * OUT_H)) + t;

    // Phase A: dependency-free zero stream — issues at warp cycle ~0,
    // overlapping the upstream param kernel (PDL) and the param load below.
    const float4 z = make_float4(0.f, 0.f, 0.f, 0.f);
    __stcs(px_addr, z);
    __stcs(py_addr, z);

    // Phase B: wait for the param kernel's writes to be visible, then
    // overwrite only the in-window float4s (~7% of the stream).
    cudaGridDependencySynchronize();

    const float4 Px = __ldg(&g_px[bn]);
    const float4 Py = __ldg(&g_py[bn]);

    const float c0 = (float)(t << 2);

    if ((c0 + 3.0f) >= Px.y && c0 < Px.z) {
        float4 vx = z;
        #pragma unroll
        for (int j = 0; j < 4; ++j) {
            float p = c0 + (float)j;
            if (p >= Px.y && p < Px.z) {
                float d = p - Px.x;
                float v = __expf(d * d * Px.w);
                if (j == 0) vx.x = v; else if (j == 1) vx.y = v;
                else if (j == 2) vx.z = v; else vx.w = v;
            }
        }
        __stcs(px_addr, vx);
    }

    if ((c0 + 3.0f) >= Py.y && c0 < Py.z) {
        float4 vy = z;
        #pragma unroll
        for (int j = 0; j < 4; ++j) {
            float p = c0 + (float)j;
            if (p >= Py.y && p < Py.z) {
                float d = p - Py.x;
                float v = __expf(d * d * Py.w);
                if (j == 0) vy.x = v; else if (j == 1) vy.y = v;
                else if (j == 2) vy.z = v; else vy.w = v;
            }
        }
        __stcs(py_addr, vy);
    }
}

extern "C" void kernel_launch(void* const* d_in, const int* in_sizes, int n_in,
                              void* d_out, int out_size)
{
    const float* centers = (const float*)d_in[0];  // [B,N,2]
    const float* whs     = (const float*)d_in[1];  // [B,N,2]
    float* out = (float*)d_out;

    const int BN = in_sizes[0] / 2;                // 128*256 = 32768
    float* out_x = out;
    float* out_y = out + (size_t)BN * OUT_W;

    gv_param_kernel<<<(BN + 255) / 256, 256>>>(centers, whs, BN);

    // Splat kernel with Programmatic Dependent Launch: CTAs may start while
    // the param kernel drains; the grid-sync inside orders the g_px reads.
    cudaLaunchAttribute attrs[1];
    attrs[0].id = cudaLaunchAttributeProgrammaticStreamSerialization;
    attrs[0].val.programmaticStreamSerializationAllowed = 1;

    cudaLaunchConfig_t cfg = {};
    cfg.gridDim  = dim3(BN, 1, 1);
    cfg.blockDim = dim3(256, 1, 1);
    cfg.dynamicSmemBytes = 0;
    cfg.stream = 0;
    cfg.attrs = attrs;
    cfg.numAttrs = 1;

    cudaLaunchKernelEx(&cfg, gv_splat_kernel, out_x, out_y);
}

// round 7
// speedup vs baseline: 1.0453x; 1.0117x over previous
#include <cuda_runtime.h>
#include <math_constants.h>

// GaussianVector_box — single-kernel store streamer.
// Per-thread param computation made cheap (no IEEE div):
//   floor(r/3) == floorf((r+0.5f)/3) for integer r (exact),
//   -0.5/s^2 via __fdividef (MUFU rcp, ~2ulp, irrelevant vs 1e-3 gate).
// So no smem / no barrier / no separate param kernel / no zero-prestore:
// every thread computes its two float4 values directly and streams them out.
// Output: [vector_x (B*N*1024)] ++ [vector_y (B*N*1024)], f32, 268 MB writes.

#define OUT_W 1024
#define OUT_H 1024

__global__ __launch_bounds__(256, 8)
void gv_box_kernel(const float* __restrict__ centers,
                   const float* __restrict__ whs,
                   float* __restrict__ out_x,
                   float* __restrict__ out_y)
{
    const int bn = blockIdx.x;
    const int t  = threadIdx.x;

    // Broadcast loads (uniform address per CTA -> single sector, L1/L2 hit).
    const float2 c  = __ldg(((const float2*)centers) + bn);
    const float2 wh = __ldg(((const float2*)whs) + bn);

    // ks = floor(W/2)*2 - 1 ; r = (ks-1)/2 = floor(W/2) - 1 (exact)
    const float rw = floorf(wh.x * 0.5f) - 1.0f;
    const float rh = floorf(wh.y * 0.5f) - 1.0f;
    // s = floor(r/3), exact for integer r via the +0.5 trick (no IEEE div)
    const float sw = floorf((rw + 0.5f) * (1.0f / 3.0f));
    const float sh = floorf((rh + 0.5f) * (1.0f / 3.0f));

    const bool zero_box = (c.x + c.y + wh.x + wh.y) == 0.0f;

    // SCALE = 1 ; astype(int32) truncates toward zero
    const float x = truncf(c.x);
    const float y = truncf(c.y);

    float ul0 = x - rw, ul1 = y - rh;
    float br0 = x + rw + 1.0f, br1 = y + rh + 1.0f;

    const bool in_ul = (ul0 >= 0.0f) & (ul0 <= (float)OUT_W) &
                       (ul1 >= 0.0f) & (ul1 <= (float)OUT_H);
    const bool in_br = (br0 >= 0.0f) & (br0 <= (float)OUT_W) &
                       (br1 >= 0.0f) & (br1 <= (float)OUT_H);

    const bool active = (!zero_box) & (sw != 0.0f) & (sh != 0.0f) & (in_ul | in_br);

    if (!active) {   // empty windows -> all lanes write zero, no exp evaluated
        ul0 = CUDART_INF_F;  br0 = -CUDART_INF_F;
        ul1 = CUDART_INF_F;  br1 = -CUDART_INF_F;
    }

    // -1/(2 sigma^2) via fast reciprocal (only consumed inside valid windows)
    const float kx = __fdividef(-0.5f, sw * sw);
    const float ky = __fdividef(-0.5f, sh * sh);

    const float c0 = (float)(t << 2);

    // ---- x row ----
    float4 vx = make_float4(0.f, 0.f, 0.f, 0.f);
    if ((c0 + 3.0f) >= ul0 && c0 < br0) {
        #pragma unroll
        for (int j = 0; j < 4; ++j) {
            float p = c0 + (float)j;
            if (p >= ul0 && p < br0) {
                float d = p - x;
                float v = __expf(d * d * kx);
                if (j == 0) vx.x = v; else if (j == 1) vx.y = v;
                else if (j == 2) vx.z = v; else vx.w = v;
            }
        }
    }

    // ---- y row ----
    float4 vy = make_float4(0.f, 0.f, 0.f, 0.f);
    if ((c0 + 3.0f) >= ul1 && c0 < br1) {
        #pragma unroll
        for (int j = 0; j < 4; ++j) {
            float p = c0 + (float)j;
            if (p >= ul1 && p < br1) {
                float d = p - y;
                float v = __expf(d * d * ky);
                if (j == 0) vy.x = v; else if (j == 1) vy.y = v;
                else if (j == 2) vy.z = v; else vy.w = v;
            }
        }
    }

    // Streaming (evict-first) 128-bit stores — 268 MB write-once stream.
    __stcs(((float4*)(out_x + (size_t)bn * OUT_W)) + t, vx);
    __stcs(((float4*)(out_y + (size_t)bn * OUT_H)) + t, vy);
}

extern "C" void kernel_launch(void* const* d_in, const int* in_sizes, int n_in,
                              void* d_out, int out_size)
{
    const float* centers = (const float*)d_in[0];  // [B,N,2]
    const float* whs     = (const float*)d_in[1];  // [B,N,2]
    float* out = (float*)d_out;

    const int BN = in_sizes[0] / 2;                // 128*256 = 32768
    float* out_x = out;
    float* out_y = out + (size_t)BN * OUT_W;

    gv_box_kernel<<<BN, 256>>>(centers, whs, out_x, out_y);
}